// round 6
// baseline (speedup 1.0000x reference)
#include <cuda_runtime.h>
#include <cuda_bf16.h>

// Problem constants
#define Bz 4
#define Nz 128
#define Mz 128
#define Dz 256
#define BDz 1024

#define KSPLIT 4
#define TSZ (Bz * Nz * Dz)      // 131072 elems (T)
#define SSZ (Bz * Nz * Mz)      // 65536 elems (S)

// Scratch in device globals (no allocation allowed).
__device__ float g_Aw[Dz * Dz];                // Aw[d][e] = sum_k A[d,e,k]*W[k]
__device__ float g_Tp[KSPLIT * TSZ];           // T partials, split over d
__device__ float g_Sp[KSPLIT * SSZ];           // S partials, split over e
__device__ int   g_cnt[16];                    // ticket counters for k3 epilogue

// ---------------------------------------------------------------------------
// Kernel 1: Aw[row] = dot(A[row*1024 .. +1024], W), row = d*256 + e
// One warp per row; W in smem; float4 streaming loads (A read exactly once).
// __launch_bounds__(256,6): cap regs at 42 -> 48 warps/SM resident.
// ---------------------------------------------------------------------------
__global__ __launch_bounds__(256, 6) void k1_reduce_A(const float* __restrict__ A,
                                                      const float* __restrict__ W) {
    __shared__ float4 sW[BDz / 4];
    int tid = threadIdx.x;
    sW[tid] = reinterpret_cast<const float4*>(W)[tid];
    __syncthreads();

    int warp = tid >> 5;
    int lane = tid & 31;
    long row = (long)blockIdx.x * 8 + warp;
    const float4* Arow = reinterpret_cast<const float4*>(A) + row * (BDz / 4);

    float acc0 = 0.0f, acc1 = 0.0f;
#pragma unroll
    for (int i = 0; i < 8; i += 2) {
        float4 a0 = __ldcs(&Arow[i * 32 + lane]);
        float4 a1 = __ldcs(&Arow[(i + 1) * 32 + lane]);
        float4 w0 = sW[i * 32 + lane];
        float4 w1 = sW[(i + 1) * 32 + lane];
        acc0 += a0.x * w0.x + a0.y * w0.y + a0.z * w0.z + a0.w * w0.w;
        acc1 += a1.x * w1.x + a1.y * w1.y + a1.z * w1.z + a1.w * w1.w;
    }
    float acc = acc0 + acc1;
#pragma unroll
    for (int off = 16; off; off >>= 1)
        acc += __shfl_xor_sync(0xffffffffu, acc, off);
    if (lane == 0) g_Aw[row] = acc;
}

// ---------------------------------------------------------------------------
// Kernel 2 (split-K): Tp[ks][r,e] = sum_{d in chunk ks} X[r,d] * Aw[d,e]
// 64x64 tile, 256 threads, 4x4 register blocking. Grid (4,8,4) = 128 blocks.
// Also resets the 16 ticket counters used by k3 (k2 strictly precedes k3).
// ---------------------------------------------------------------------------
__global__ __launch_bounds__(256) void k2_split(const float* __restrict__ X) {
    __shared__ float sX[64][65];   // [r][k]
    __shared__ float sA[64][65];   // [k][e]

    int tid = threadIdx.x;
    if (blockIdx.x == 0 && blockIdx.y == 0 && blockIdx.z == 0 && tid < 16)
        g_cnt[tid] = 0;

    int tx = tid & 15;            // e group
    int ty = tid >> 4;            // r group
    int e0 = blockIdx.x * 64;
    int r0 = blockIdx.y * 64;
    int ks = blockIdx.z;
    int kc = ks * 64;

#pragma unroll
    for (int t = 0; t < 4; t++) {
        int lin = tid + t * 256;
        int row = lin >> 4;
        int c4  = (lin & 15) << 2;
        float4 xv = *reinterpret_cast<const float4*>(&X[(r0 + row) * Dz + kc + c4]);
        sX[row][c4 + 0] = xv.x; sX[row][c4 + 1] = xv.y;
        sX[row][c4 + 2] = xv.z; sX[row][c4 + 3] = xv.w;
        float4 av = *reinterpret_cast<const float4*>(&g_Aw[(kc + row) * Dz + e0 + c4]);
        sA[row][c4 + 0] = av.x; sA[row][c4 + 1] = av.y;
        sA[row][c4 + 2] = av.z; sA[row][c4 + 3] = av.w;
    }
    __syncthreads();

    float acc[4][4] = {};
#pragma unroll 16
    for (int k = 0; k < 64; k++) {
        float xv[4], av[4];
#pragma unroll
        for (int i = 0; i < 4; i++) xv[i] = sX[ty + 16 * i][k];
#pragma unroll
        for (int j = 0; j < 4; j++) av[j] = sA[k][tx + 16 * j];
#pragma unroll
        for (int i = 0; i < 4; i++)
#pragma unroll
            for (int j = 0; j < 4; j++)
                acc[i][j] += xv[i] * av[j];
    }

    float* out = g_Tp + (long)ks * TSZ;
#pragma unroll
    for (int i = 0; i < 4; i++)
#pragma unroll
        for (int j = 0; j < 4; j++)
            out[(r0 + ty + 16 * i) * Dz + e0 + tx + 16 * j] = acc[i][j];
}

// ---------------------------------------------------------------------------
// Kernel 3 (split-K over e, fused epilogue):
//   Sp[ks][b,n,m] = sum_{e chunk} T[b,n,e]*Y[b,m,e]
//   T reconstructed from the 4 d-partials during the smem load (L2-hot).
//   Last block of each (m-tile,n-tile,b) group sums the 4 Sp partials in
//   fixed ks order (deterministic) and writes S + bias. No k4.
// Grid: (2, 2, 16) = 64 blocks.
// ---------------------------------------------------------------------------
__global__ __launch_bounds__(256) void k3_split(const float* __restrict__ Y,
                                                const float* __restrict__ bias,
                                                float* __restrict__ S) {
    __shared__ float sT[64][65];   // [n][e]
    __shared__ float sY[64][65];   // [m][e]
    __shared__ int   sLast;

    int tid = threadIdx.x;
    int tx = tid & 15;            // m group
    int ty = tid >> 4;            // n group
    int m0 = blockIdx.x * 64;
    int n0 = blockIdx.y * 64;
    int b  = blockIdx.z >> 2;
    int ks = blockIdx.z & 3;
    int kc = ks * 64;             // e chunk
    int gid = ((b * 2 + blockIdx.y) * 2 + blockIdx.x);   // 0..15

    long tb = (long)b * Nz * Dz;
    const float* Yb = Y + (long)b * Mz * Dz;

#pragma unroll
    for (int t = 0; t < 4; t++) {
        int lin = tid + t * 256;
        int row = lin >> 4;
        int c4  = (lin & 15) << 2;
        long base = tb + (long)(n0 + row) * Dz + kc + c4;
        float4 t0 = *reinterpret_cast<const float4*>(&g_Tp[0 * TSZ + base]);
        float4 t1 = *reinterpret_cast<const float4*>(&g_Tp[1 * TSZ + base]);
        float4 t2 = *reinterpret_cast<const float4*>(&g_Tp[2 * TSZ + base]);
        float4 t3 = *reinterpret_cast<const float4*>(&g_Tp[3 * TSZ + base]);
        sT[row][c4 + 0] = t0.x + t1.x + t2.x + t3.x;
        sT[row][c4 + 1] = t0.y + t1.y + t2.y + t3.y;
        sT[row][c4 + 2] = t0.z + t1.z + t2.z + t3.z;
        sT[row][c4 + 3] = t0.w + t1.w + t2.w + t3.w;
        float4 yv = *reinterpret_cast<const float4*>(&Yb[(long)(m0 + row) * Dz + kc + c4]);
        sY[row][c4 + 0] = yv.x; sY[row][c4 + 1] = yv.y;
        sY[row][c4 + 2] = yv.z; sY[row][c4 + 3] = yv.w;
    }
    __syncthreads();

    float acc[4][4] = {};
#pragma unroll 16
    for (int e = 0; e < 64; e++) {
        float tv[4], yv[4];
#pragma unroll
        for (int i = 0; i < 4; i++) tv[i] = sT[ty + 16 * i][e];
#pragma unroll
        for (int j = 0; j < 4; j++) yv[j] = sY[tx + 16 * j][e];
#pragma unroll
        for (int i = 0; i < 4; i++)
#pragma unroll
            for (int j = 0; j < 4; j++)
                acc[i][j] += tv[i] * yv[j];
    }

    long sbase = (long)b * Nz * Mz;
    float* out = g_Sp + (long)ks * SSZ + sbase;
#pragma unroll
    for (int i = 0; i < 4; i++)
#pragma unroll
        for (int j = 0; j < 4; j++)
            out[(n0 + ty + 16 * i) * Mz + m0 + tx + 16 * j] = acc[i][j];

    // --- fused deterministic reduction: last block of this tile group ---
    __threadfence();
    __syncthreads();
    if (tid == 0) sLast = (atomicAdd(&g_cnt[gid], 1) == KSPLIT - 1);
    __syncthreads();
    if (sLast) {
        float bv = bias[0];
#pragma unroll
        for (int t = 0; t < 4; t++) {
            int lin = tid + t * 256;          // 0..1023 float4 slots
            int row = lin >> 4;               // 0..63
            int c4  = (lin & 15) << 2;        // 0..60
            long p = sbase + (long)(n0 + row) * Mz + m0 + c4;
            float4 a0 = *reinterpret_cast<const float4*>(&g_Sp[0 * SSZ + p]);
            float4 a1 = *reinterpret_cast<const float4*>(&g_Sp[1 * SSZ + p]);
            float4 a2 = *reinterpret_cast<const float4*>(&g_Sp[2 * SSZ + p]);
            float4 a3 = *reinterpret_cast<const float4*>(&g_Sp[3 * SSZ + p]);
            float4 r;
            r.x = a0.x + a1.x + a2.x + a3.x + bv;
            r.y = a0.y + a1.y + a2.y + a3.y + bv;
            r.z = a0.z + a1.z + a2.z + a3.z + bv;
            r.w = a0.w + a1.w + a2.w + a3.w + bv;
            *reinterpret_cast<float4*>(&S[p]) = r;
        }
    }
}

// ---------------------------------------------------------------------------
// Launch: inputs in order X, Y, A, W, b
// ---------------------------------------------------------------------------
extern "C" void kernel_launch(void* const* d_in, const int* in_sizes, int n_in,
                              void* d_out, int out_size) {
    const float* X = (const float*)d_in[0];  // [4,128,256]
    const float* Y = (const float*)d_in[1];  // [4,128,256]
    const float* A = (const float*)d_in[2];  // [256,256,1024]
    const float* W = (const float*)d_in[3];  // [1,1024]
    const float* b = (const float*)d_in[4];  // [1]
    float* S = (float*)d_out;                // [4,128,128]

    k1_reduce_A<<<8192, 256>>>(A, W);

    {
        dim3 grid(Dz / 64, (Bz * Nz) / 64, KSPLIT);   // (4, 8, 4) = 128 blocks
        k2_split<<<grid, 256>>>(X);
    }
    {
        dim3 grid(Mz / 64, Nz / 64, Bz * KSPLIT);     // (2, 2, 16) = 64 blocks
        k3_split<<<grid, 256>>>(Y, b, S);
    }
}